// round 13
// baseline (speedup 1.0000x reference)
#include <cuda_runtime.h>
#include <cuda_fp8.h>
#include <cstdint>

// ---------------------------------------------------------------------------
// Problem constants
// ---------------------------------------------------------------------------
#define B_ROWS  16384
#define D_DIM   784
#define C_DIM   2048
#define OUT_DIM 10

#define KPAD   800               // 784 padded to 25*32 (fp8 bytes)
#define KWORDS 200               // KPAD/4
#define ROWB   800               // bytes per row
#define KB     160               // K bytes per pipeline block
#define NKBLK  5                 // blocks per chunk (5*160 = 800)
#define NK32   5                 // k32 steps per block
#define TM     128               // x rows per unit
#define TN     128               // centres per chunk
#define NSLICE 8                 // C split across units
#define CHPS   2                 // chunks per unit (256 centres)
#define BPU    (CHPS * NKBLK)    // 10 blocks per unit
#define NUNITS ((B_ROWS / TM) * NSLICE)   // 1024 work units
#define NTHREADS 256

// smem tile stride: 160 data + 16 pad bytes (ldmatrix phases conflict-free)
#define ASTB  176
#define TILEB 22528u             // 128 * 176
#define NSTAGE 3
#define WST   12                 // floats per Wcol row (10 + 2 pad)

// smem byte offsets (metadata double-buffered by chunk parity)
#define OFF_A    0u                       // 3 x 22528 = 67584
#define OFF_B    67584u                   // 3 x 22528 = 67584
#define OFF_WCOL 135168u                  // 2 x 128 x 12 x 4 = 12288
#define OFF_C2   147456u                  // 2 x 128 x 4 = 1024
#define OFF_IS2  148480u                  // 2 x 128 x 4 = 1024
#define OFF_RED  149504u                  // 128 x 12 x 4 = 6144
#define SMEM_TOTAL 155648u

// ---------------------------------------------------------------------------
// Device-global scratch (no allocations allowed)
// ---------------------------------------------------------------------------
__device__ __align__(16) uint32_t g_xq[(size_t)B_ROWS * KWORDS];   // 13.1 MB fp8
__device__ __align__(16) uint32_t g_cq[(size_t)C_DIM * KWORDS];    // 1.6 MB fp8
__device__ float g_x2[B_ROWS];
__device__ float g_c2[C_DIM];
__device__ float g_is2[C_DIM];
__device__ __align__(16) float g_part[(size_t)NSLICE * B_ROWS * OUT_DIM]; // 5.2 MB

// ---------------------------------------------------------------------------
// PTX helpers (base-ISA sm_80/89 era; valid for compute_103 virtual arch)
// ---------------------------------------------------------------------------
__device__ __forceinline__ uint32_t smem_u32(const void* p) {
    uint32_t a;
    asm("{ .reg .u64 t; cvta.to.shared.u64 t, %1; cvt.u32.u64 %0, t; }" : "=r"(a) : "l"(p));
    return a;
}

__device__ __forceinline__ void cp16(uint32_t dst, const void* src) {
    asm volatile("cp.async.cg.shared.global [%0], [%1], 16;" :: "r"(dst), "l"(src));
}
#define CP_COMMIT() asm volatile("cp.async.commit_group;" ::: "memory")
#define CP_WAIT0()  asm volatile("cp.async.wait_group 0;"  ::: "memory")
#define CP_WAIT1()  asm volatile("cp.async.wait_group 1;"  ::: "memory")

__device__ __forceinline__ void ldm_x4(uint32_t* r, uint32_t addr) {
    asm volatile("ldmatrix.sync.aligned.m8n8.x4.shared.b16 {%0,%1,%2,%3}, [%4];"
                 : "=r"(r[0]), "=r"(r[1]), "=r"(r[2]), "=r"(r[3]) : "r"(addr));
}

// fp8 e4m3 MMA: m16n8k32, f32 accum (sm_89+ base ISA)
__device__ __forceinline__ void mma16832_fp8(float* c, const uint32_t* a, const uint32_t* b) {
    asm volatile(
        "mma.sync.aligned.m16n8k32.row.col.f32.e4m3.e4m3.f32 "
        "{%0,%1,%2,%3}, {%4,%5,%6,%7}, {%8,%9}, {%0,%1,%2,%3};"
        : "+f"(c[0]), "+f"(c[1]), "+f"(c[2]), "+f"(c[3])
        : "r"(a[0]), "r"(a[1]), "r"(a[2]), "r"(a[3]), "r"(b[0]), "r"(b[1]));
}

__device__ __forceinline__ uint32_t quad_to_fp8(float4 v) {
    __nv_fp8x2_storage_t lo = __nv_cvt_float2_to_fp8x2(make_float2(v.x, v.y),
                                                       __NV_SATFINITE, __NV_E4M3);
    __nv_fp8x2_storage_t hi = __nv_cvt_float2_to_fp8x2(make_float2(v.z, v.w),
                                                       __NV_SATFINITE, __NV_E4M3);
    return (uint32_t)lo | ((uint32_t)hi << 16);
}

// ---------------------------------------------------------------------------
// Fused prep: fp8 conversion (padded) + row squared norms.
// Two adjacent rows per warp (proven 13.4us; at mixed R/W HBM floor).
// ---------------------------------------------------------------------------
__global__ __launch_bounds__(256)
void prep_kernel(const float* __restrict__ x,
                 const float* __restrict__ c,
                 const float* __restrict__ ls) {
    const int gw   = (blockIdx.x * blockDim.x + threadIdx.x) >> 5;
    const int lane = threadIdx.x & 31;
    const int NPAIR = (B_ROWS + C_DIM) / 2;          // 9216
    if (gw >= NPAIR) return;

    const int r0   = gw * 2;
    const bool isX = r0 < B_ROWS;
    const int row0 = isX ? r0 : r0 - B_ROWS;

    const float4* s0 = (const float4*)((isX ? x : c) + (size_t)row0 * D_DIM);
    const float4* s1 = s0 + D_DIM / 4;
    uint32_t* d0 = (isX ? g_xq : g_cq) + (size_t)row0 * KWORDS;
    uint32_t* d1 = d0 + KWORDS;

    float4 v0[7], v1[7];
    #pragma unroll
    for (int i = 0; i < 6; i++) { v0[i] = s0[lane + i * 32]; v1[i] = s1[lane + i * 32]; }
    const int wt = 192 + lane;
    v0[6] = (lane < 4) ? s0[wt] : make_float4(0.f, 0.f, 0.f, 0.f);
    v1[6] = (lane < 4) ? s1[wt] : make_float4(0.f, 0.f, 0.f, 0.f);

    float n0 = 0.f, n1 = 0.f;
    #pragma unroll
    for (int i = 0; i < 7; i++) {
        n0 = fmaf(v0[i].x, v0[i].x, fmaf(v0[i].y, v0[i].y,
             fmaf(v0[i].z, v0[i].z, fmaf(v0[i].w, v0[i].w, n0))));
        n1 = fmaf(v1[i].x, v1[i].x, fmaf(v1[i].y, v1[i].y,
             fmaf(v1[i].z, v1[i].z, fmaf(v1[i].w, v1[i].w, n1))));
    }

    #pragma unroll
    for (int i = 0; i < 6; i++) {
        d0[lane + i * 32] = quad_to_fp8(v0[i]);
        d1[lane + i * 32] = quad_to_fp8(v1[i]);
    }
    if (lane < 8) { d0[wt] = quad_to_fp8(v0[6]); d1[wt] = quad_to_fp8(v1[6]); }

    #pragma unroll
    for (int m = 16; m; m >>= 1) {
        n0 += __shfl_xor_sync(0xffffffffu, n0, m);
        n1 += __shfl_xor_sync(0xffffffffu, n1, m);
    }
    if (lane == 0) {
        if (isX) { g_x2[row0] = n0; g_x2[row0 + 1] = n1; }
        else {
            g_c2[row0]     = n0; g_is2[row0]     = __expf(-2.f * ls[row0]);
            g_c2[row0 + 1] = n1; g_is2[row0 + 1] = __expf(-2.f * ls[row0 + 1]);
        }
    }
}

// ---------------------------------------------------------------------------
// Per-block address helper (R9-proven recompute-per-block style)
// ---------------------------------------------------------------------------
struct BlkA { int m0, n0, koff, kb, cl, unit; };
__device__ __forceinline__ BlkA blk_addr(int gb, int cta, int stride) {
    BlkA b;
    const int ui  = gb / BPU;
    const int rem = gb - ui * BPU;
    b.cl   = rem / NKBLK;
    b.kb   = rem - b.cl * NKBLK;
    b.unit = cta + ui * stride;
    b.m0   = (b.unit >> 3) * TM;
    b.n0   = ((b.unit & (NSLICE - 1)) * CHPS + b.cl) * TN;
    b.koff = b.kb * KB;
    return b;
}

__device__ __forceinline__ void issue_tile(uint32_t sbase, int buf, const BlkA& b, int tid) {
    const uint32_t aO = sbase + OFF_A + (uint32_t)buf * TILEB;
    const uint32_t bO = sbase + OFF_B + (uint32_t)buf * TILEB;
    const char* xb = (const char*)g_xq + (size_t)b.m0 * ROWB + b.koff;
    const char* cb = (const char*)g_cq + (size_t)b.n0 * ROWB + b.koff;
    #pragma unroll
    for (int i = 0; i < 5; i++) {
        const int idx = tid + i * NTHREADS;        // 0..1279
        const int r = idx / 10, ch = idx - r * 10;
        cp16(aO + (uint32_t)(r * ASTB + ch * 16), xb + (size_t)(r * ROWB + ch * 16));
        cp16(bO + (uint32_t)(r * ASTB + ch * 16), cb + (size_t)(r * ROWB + ch * 16));
    }
    CP_COMMIT();
}

// ---------------------------------------------------------------------------
// Persistent main kernel: R9 skeleton (256 thr, 32x64 warp tiles, 3-stage)
// + chunk-parity double-buffered metadata prefetched during MMA blocks.
// ---------------------------------------------------------------------------
__global__ __launch_bounds__(NTHREADS, 1)
void rbf_mma_kernel(const float* __restrict__ W) {
    extern __shared__ char sm[];
    const uint32_t sbase = smem_u32(sm);

    const int tid  = threadIdx.x;
    const int wid  = tid >> 5;
    const int lane = tid & 31;
    const int wm   = wid & 3;
    const int wn   = wid >> 2;
    const int lm   = lane >> 2;
    const int ln   = (lane & 3) * 2;
    const int cta  = blockIdx.x;
    const int strd = gridDim.x;

    float* c2B   = (float*)(sm + OFF_C2);     // [2][TN]
    float* is2B  = (float*)(sm + OFF_IS2);    // [2][TN]
    float* WcolB = (float*)(sm + OFF_WCOL);   // [2][TN*WST]
    float* redS  = (float*)(sm + OFF_RED);

    const int n_units = (NUNITS - cta + strd - 1) / strd;
    if (n_units <= 0) return;
    const int NB = n_units * BPU;

    const uint32_t lrow  = (uint32_t)(lane & 15);
    const uint32_t lcol  = (uint32_t)(lane >> 4) * 16u;

    // prologue: 2 tiles in flight + chunk 0 metadata into buffer 0
    issue_tile(sbase, 0, blk_addr(0, cta, strd), tid);
    if (NB > 1) issue_tile(sbase, 1, blk_addr(1, cta, strd), tid);
    {
        const int n00 = (cta & (NSLICE - 1)) * (CHPS * TN);
        if (tid < TN) {
            c2B[tid]  = g_c2[n00 + tid];
            is2B[tid] = g_is2[n00 + tid];
        }
        #pragma unroll
        for (int it = 0; it < 5; it++) {
            const int idx = tid + it * NTHREADS;   // 0..1279
            const int cc = idx / 10, o = idx - cc * 10;
            WcolB[cc * WST + o] = W[(size_t)o * C_DIM + n00 + cc];
        }
    }

    float oacc[4][OUT_DIM];
    #pragma unroll
    for (int i = 0; i < 4; i++)
        #pragma unroll
        for (int o = 0; o < OUT_DIM; o++) oacc[i][o] = 0.f;

    float acc[2][8][4];
    float x2a0 = 0.f, x2b0 = 0.f, x2a1 = 0.f, x2b1 = 0.f;

    for (int gb = 0; gb < NB; gb++) {
        const BlkA b = blk_addr(gb, cta, strd);
        const int buf = gb % NSTAGE;

        if (b.kb == 0) {
            if (b.cl == 0) {
                const int ra0 = b.m0 + wm * 32 + lm;
                x2a0 = g_x2[ra0];      x2b0 = g_x2[ra0 + 8];
                x2a1 = g_x2[ra0 + 16]; x2b1 = g_x2[ra0 + 24];
            }
            #pragma unroll
            for (int i = 0; i < 2; i++)
                #pragma unroll
                for (int j = 0; j < 8; j++)
                    #pragma unroll
                    for (int e = 0; e < 4; e++) acc[i][j][e] = 0.f;
        }

        if (gb + 1 < NB) CP_WAIT1(); else CP_WAIT0();
        __syncthreads();   // tile visible CTA-wide; also orders meta buffers

        if (gb + 2 < NB)
            issue_tile(sbase, (gb + 2) % NSTAGE, blk_addr(gb + 2, cta, strd), tid);

        // ---- prefetch NEXT chunk's metadata into buffer cl^1 (kb 0..3) ----
        // Writes complete before the kb==4 block's sync; epilogue reads buffer
        // cl only. Buffer cl is rewritten two chunks later, behind syncs.
        if (b.kb < 4) {
            const bool next_exists = (b.cl == 0) || (b.unit + strd < NUNITS);
            if (next_exists) {
                const int nn0 = (b.cl == 0)
                    ? (b.n0 + TN)
                    : (((b.unit + strd) & (NSLICE - 1)) * (CHPS * TN));
                float* Wn = WcolB + (b.cl ^ 1) * (TN * WST);
                if (b.kb == 0) {
                    if (tid < TN) {
                        c2B[(b.cl ^ 1) * TN + tid]  = g_c2[nn0 + tid];
                        is2B[(b.cl ^ 1) * TN + tid] = g_is2[nn0 + tid];
                    }
                    #pragma unroll
                    for (int it = 0; it < 2; it++) {
                        const int idx = tid + it * NTHREADS;
                        const int cc = idx / 10, o = idx - cc * 10;
                        Wn[cc * WST + o] = W[(size_t)o * C_DIM + nn0 + cc];
                    }
                } else {
                    const int idx = tid + (b.kb + 1) * NTHREADS;  // iters 2,3,4
                    const int cc = idx / 10, o = idx - cc * 10;
                    Wn[cc * WST + o] = W[(size_t)o * C_DIM + nn0 + cc];
                }
            }
        }

        const uint32_t aBase = sbase + OFF_A + (uint32_t)buf * TILEB;
        const uint32_t bBase = sbase + OFF_B + (uint32_t)buf * TILEB;

        #pragma unroll
        for (int ks = 0; ks < NK32; ks++) {
            uint32_t af[2][4];
            #pragma unroll
            for (int mi = 0; mi < 2; mi++)
                ldm_x4(af[mi], aBase + (uint32_t)(wm * 32 + mi * 16 + lrow) * ASTB
                                     + (uint32_t)ks * 32u + lcol);
            uint32_t bf[8][2];
            #pragma unroll
            for (int njj = 0; njj < 4; njj++) {
                uint32_t r4[4];
                ldm_x4(r4, bBase + (uint32_t)(wn * 64 + njj * 16 + lrow) * ASTB
                                 + (uint32_t)ks * 32u + lcol);
                bf[njj * 2 + 0][0] = r4[0];
                bf[njj * 2 + 1][0] = r4[1];
                bf[njj * 2 + 0][1] = r4[2];
                bf[njj * 2 + 1][1] = r4[3];
            }
            #pragma unroll
            for (int mi = 0; mi < 2; mi++)
                #pragma unroll
                for (int nf = 0; nf < 8; nf++)
                    mma16832_fp8(acc[mi][nf], af[mi], bf[nf]);
        }

        if (b.kb == NKBLK - 1) {
            // ---- chunk epilogue (reads meta buffer b.cl) ----
            const float* c2S   = c2B  + b.cl * TN;
            const float* is2S  = is2B + b.cl * TN;
            const float* WcolS = WcolB + b.cl * (TN * WST);
            #pragma unroll
            for (int nf = 0; nf < 8; nf++) {
                const int c0 = wn * 64 + nf * 8 + ln;
                const int c1 = c0 + 1;
                const float cc0 = c2S[c0],  cc1 = c2S[c1];
                const float ii0 = is2S[c0], ii1 = is2S[c1];
                #pragma unroll
                for (int mi = 0; mi < 2; mi++) {
                    const float xa = mi ? x2a1 : x2a0;
                    const float xb = mi ? x2b1 : x2b0;
                    const float t00 = fmaxf(xa + cc0 - 2.f * acc[mi][nf][0], 0.f) * ii0;
                    const float t01 = fmaxf(xa + cc1 - 2.f * acc[mi][nf][1], 0.f) * ii1;
                    const float t10 = fmaxf(xb + cc0 - 2.f * acc[mi][nf][2], 0.f) * ii0;
                    const float t11 = fmaxf(xb + cc1 - 2.f * acc[mi][nf][3], 0.f) * ii1;
                    if (t00 < 104.f || t01 < 104.f || t10 < 104.f || t11 < 104.f) {
                        const float p00 = __expf(-t00);
                        const float p01 = __expf(-t01);
                        const float p10 = __expf(-t10);
                        const float p11 = __expf(-t11);
                        #pragma unroll
                        for (int o = 0; o < OUT_DIM; o++) {
                            const float w0 = WcolS[c0 * WST + o];
                            const float w1 = WcolS[c1 * WST + o];
                            oacc[mi * 2 + 0][o] = fmaf(p00, w0, fmaf(p01, w1, oacc[mi * 2 + 0][o]));
                            oacc[mi * 2 + 1][o] = fmaf(p10, w0, fmaf(p11, w1, oacc[mi * 2 + 1][o]));
                        }
                    }
                }
            }
            // no sync needed: next chunk writes the OTHER metadata buffer

            if (b.cl == CHPS - 1) {
                // ---- unit-end: cross-lane + cross-warp reduce, write partial ----
                #pragma unroll
                for (int i = 0; i < 4; i++)
                    #pragma unroll
                    for (int o = 0; o < OUT_DIM; o++) {
                        float v = oacc[i][o];
                        v += __shfl_xor_sync(0xffffffffu, v, 1);
                        v += __shfl_xor_sync(0xffffffffu, v, 2);
                        oacc[i][o] = v;
                    }
                if (wn == 0 && (lane & 3) == 0) {
                    #pragma unroll
                    for (int i = 0; i < 4; i++) {
                        const int r = wm * 32 + (i >> 1) * 16 + (i & 1) * 8 + lm;
                        #pragma unroll
                        for (int o = 0; o < OUT_DIM; o++) redS[r * WST + o] = oacc[i][o];
                    }
                }
                __syncthreads();
                if (wn == 1 && (lane & 3) == 0) {
                    #pragma unroll
                    for (int i = 0; i < 4; i++) {
                        const int r = wm * 32 + (i >> 1) * 16 + (i & 1) * 8 + lm;
                        #pragma unroll
                        for (int o = 0; o < OUT_DIM; o++) redS[r * WST + o] += oacc[i][o];
                    }
                }
                __syncthreads();

                const int slice = b.unit & (NSLICE - 1);
                float* pbase = g_part + (size_t)slice * B_ROWS * OUT_DIM
                             + (size_t)b.m0 * OUT_DIM;
                #pragma unroll
                for (int i = 0; i < 5; i++) {
                    const int e = tid + i * NTHREADS;
                    const int r = e / 10, o = e - r * 10;
                    pbase[e] = redS[r * WST + o];
                }
                #pragma unroll
                for (int i = 0; i < 4; i++)
                    #pragma unroll
                    for (int o = 0; o < OUT_DIM; o++) oacc[i][o] = 0.f;
                // redS reuse is CHPS*NKBLK blocks away, behind per-block syncs
            }
        }
    }
}

// ---------------------------------------------------------------------------
// Reduce: out = sum of 8 slice partials + bias  (float4 vectorized)
// ---------------------------------------------------------------------------
__global__ void reduce_kernel(const float* __restrict__ bias, float* __restrict__ out) {
    const int t = blockIdx.x * blockDim.x + threadIdx.x;       // float4 index
    const int NQ = (B_ROWS * OUT_DIM) / 4;                     // 40960
    if (t >= NQ) return;
    const int i0 = t * 4;
    float4 s;
    s.x = __ldg(&bias[(i0 + 0) % OUT_DIM]);
    s.y = __ldg(&bias[(i0 + 1) % OUT_DIM]);
    s.z = __ldg(&bias[(i0 + 2) % OUT_DIM]);
    s.w = __ldg(&bias[(i0 + 3) % OUT_DIM]);
    #pragma unroll
    for (int sl = 0; sl < NSLICE; sl++) {
        const float4 p = *(const float4*)&g_part[(size_t)sl * B_ROWS * OUT_DIM + i0];
        s.x += p.x; s.y += p.y; s.z += p.z; s.w += p.w;
    }
    ((float4*)out)[t] = s;
}

// ---------------------------------------------------------------------------
// Launch
// ---------------------------------------------------------------------------
extern "C" void kernel_launch(void* const* d_in, const int* in_sizes, int n_in,
                              void* d_out, int out_size) {
    const float* x       = (const float*)d_in[0];
    const float* centres = (const float*)d_in[1];
    const float* ls      = (const float*)d_in[2];
    const float* W       = (const float*)d_in[3];
    const float* bias    = (const float*)d_in[4];
    float* out           = (float*)d_out;

    int nsm = 148;
    cudaDeviceGetAttribute(&nsm, cudaDevAttrMultiProcessorCount, 0);

    const int npairs = (B_ROWS + C_DIM) / 2;        // 9216 warp work items
    prep_kernel<<<(npairs + 7) / 8, 256>>>(x, centres, ls);

    cudaFuncSetAttribute(rbf_mma_kernel,
                         cudaFuncAttributeMaxDynamicSharedMemorySize, SMEM_TOTAL);
    rbf_mma_kernel<<<nsm, NTHREADS, SMEM_TOTAL>>>(W);

    reduce_kernel<<<((B_ROWS * OUT_DIM) / 4 + 255) / 256, 256>>>(bias, out);
}

// round 14
// speedup vs baseline: 1.0885x; 1.0885x over previous
#include <cuda_runtime.h>
#include <cuda_fp8.h>
#include <cstdint>

// ---------------------------------------------------------------------------
// Problem constants
// ---------------------------------------------------------------------------
#define B_ROWS  16384
#define D_DIM   784
#define C_DIM   2048
#define OUT_DIM 10

#define KPAD   800               // 784 padded to 25*32 (fp8 bytes)
#define KWORDS 200               // KPAD/4
#define KB     160               // K bytes per pipeline block
#define NKBLK  5                 // blocks per chunk (5*160 = 800)
#define NK32   5                 // k32 steps per block
#define TM     128               // x rows per unit
#define TN     128               // centres per chunk
#define NSLICE 8                 // C split across units
#define CHPS   2                 // chunks per unit (256 centres)
#define BPU    (CHPS * NKBLK)    // 10 blocks per unit
#define NUNITS ((B_ROWS / TM) * NSLICE)   // 1024 work units
#define NTHREADS 256

// smem tile stride: 160 data + 16 pad bytes (ldmatrix phases r*11 mod 8 distinct)
#define ASTB  176
#define TILEB 22528u             // 128 * 176
#define NSTAGE 3
#define WST   12                 // floats per Wcol row (10 + 2 pad)

// smem byte offsets
#define OFF_A    0u                       // 3 x 22528 = 67584
#define OFF_B    67584u                   // 3 x 22528 = 67584
#define OFF_WCOL 135168u                  // 128 x 12 x 4 = 6144
#define OFF_C2   141312u                  // 128 x 4
#define OFF_IS2  141824u
#define OFF_RED  142336u                  // 128 x 12 x 4 = 6144
#define SMEM_TOTAL 148480u

// ---------------------------------------------------------------------------
// Device-global scratch (no allocations allowed)
// ---------------------------------------------------------------------------
__device__ __align__(16) uint32_t g_xq[(size_t)B_ROWS * KWORDS];   // 13.1 MB fp8
__device__ __align__(16) uint32_t g_cq[(size_t)C_DIM * KWORDS];    // 1.6 MB fp8
__device__ float g_x2[B_ROWS];
__device__ float g_c2[C_DIM];
__device__ float g_is2[C_DIM];
__device__ __align__(16) float g_part[(size_t)NSLICE * B_ROWS * OUT_DIM]; // 5.2 MB

// ---------------------------------------------------------------------------
// PTX helpers (base-ISA sm_80/89 era; valid for compute_103 virtual arch)
// ---------------------------------------------------------------------------
__device__ __forceinline__ uint32_t smem_u32(const void* p) {
    uint32_t a;
    asm("{ .reg .u64 t; cvta.to.shared.u64 t, %1; cvt.u32.u64 %0, t; }" : "=r"(a) : "l"(p));
    return a;
}

__device__ __forceinline__ void cp16(uint32_t dst, const void* src) {
    asm volatile("cp.async.cg.shared.global [%0], [%1], 16;" :: "r"(dst), "l"(src));
}
#define CP_COMMIT() asm volatile("cp.async.commit_group;" ::: "memory")
#define CP_WAIT0()  asm volatile("cp.async.wait_group 0;"  ::: "memory")
#define CP_WAIT1()  asm volatile("cp.async.wait_group 1;"  ::: "memory")

__device__ __forceinline__ void ldm_x4(uint32_t* r, uint32_t addr) {
    asm volatile("ldmatrix.sync.aligned.m8n8.x4.shared.b16 {%0,%1,%2,%3}, [%4];"
                 : "=r"(r[0]), "=r"(r[1]), "=r"(r[2]), "=r"(r[3]) : "r"(addr));
}

// fp8 e4m3 MMA: m16n8k32, f32 accum (sm_89+ base ISA; full SIMT rate on sm_103a)
__device__ __forceinline__ void mma16832_fp8(float* c, const uint32_t* a, const uint32_t* b) {
    asm volatile(
        "mma.sync.aligned.m16n8k32.row.col.f32.e4m3.e4m3.f32 "
        "{%0,%1,%2,%3}, {%4,%5,%6,%7}, {%8,%9}, {%0,%1,%2,%3};"
        : "+f"(c[0]), "+f"(c[1]), "+f"(c[2]), "+f"(c[3])
        : "r"(a[0]), "r"(a[1]), "r"(a[2]), "r"(a[3]), "r"(b[0]), "r"(b[1]));
}

__device__ __forceinline__ uint32_t quad_to_fp8(float4 v) {
    __nv_fp8x2_storage_t lo = __nv_cvt_float2_to_fp8x2(make_float2(v.x, v.y),
                                                       __NV_SATFINITE, __NV_E4M3);
    __nv_fp8x2_storage_t hi = __nv_cvt_float2_to_fp8x2(make_float2(v.z, v.w),
                                                       __NV_SATFINITE, __NV_E4M3);
    return (uint32_t)lo | ((uint32_t)hi << 16);
}

// ---------------------------------------------------------------------------
// Fused prep: fp8 conversion (padded) + row squared norms. One warp per row;
// handles both x (rows < B_ROWS) and centres.
// ---------------------------------------------------------------------------
__global__ __launch_bounds__(256)
void prep_kernel(const float* __restrict__ x,
                 const float* __restrict__ c,
                 const float* __restrict__ ls) {
    const int gw   = (blockIdx.x * blockDim.x + threadIdx.x) >> 5;
    const int lane = threadIdx.x & 31;
    const bool isX = gw < B_ROWS;
    const int row  = isX ? gw : gw - B_ROWS;
    if (!isX && row >= C_DIM) return;

    const float4* src = (const float4*)((isX ? x : c) + (size_t)row * D_DIM);
    uint32_t* dst = (isX ? g_xq : g_cq) + (size_t)row * KWORDS;

    // 196 data words + 4 pad words. 6 full warp-iterations (192 words), then
    // a uniform tail: lanes 0..7 cover words 192..199 (196..199 zero-padded).
    float4 v[7];
    #pragma unroll
    for (int i = 0; i < 6; i++) v[i] = src[lane + i * 32];
    const int wt = 192 + lane;
    v[6] = (lane < 4) ? src[wt] : make_float4(0.f, 0.f, 0.f, 0.f);

    float s = 0.f;
    #pragma unroll
    for (int i = 0; i < 7; i++)
        s = fmaf(v[i].x, v[i].x, fmaf(v[i].y, v[i].y,
            fmaf(v[i].z, v[i].z, fmaf(v[i].w, v[i].w, s))));

    #pragma unroll
    for (int i = 0; i < 6; i++) dst[lane + i * 32] = quad_to_fp8(v[i]);
    if (lane < 8) dst[wt] = quad_to_fp8(v[6]);   // words 196..199 write zeros

    #pragma unroll
    for (int m = 16; m; m >>= 1) s += __shfl_xor_sync(0xffffffffu, s, m);
    if (lane == 0) {
        if (isX) g_x2[row] = s;
        else     { g_c2[row] = s; g_is2[row] = __expf(-2.f * ls[row]); }
    }
}

// ---------------------------------------------------------------------------
// Per-block address helper for the flattened persistent pipeline
// gb (per-CTA block idx) -> unit/chunk/kblock -> global tile addresses
// ---------------------------------------------------------------------------
struct BlkA { int m0, n0, koff, kb, cl, unit; };
__device__ __forceinline__ BlkA blk_addr(int gb, int cta, int stride) {
    BlkA b;
    const int ui  = gb / BPU;
    const int rem = gb - ui * BPU;
    b.cl   = rem / NKBLK;
    b.kb   = rem - b.cl * NKBLK;
    b.unit = cta + ui * stride;
    b.m0   = (b.unit >> 3) * TM;
    b.n0   = ((b.unit & (NSLICE - 1)) * CHPS + b.cl) * TN;
    b.koff = b.kb * KB;
    return b;
}

__device__ __forceinline__ void issue_tile(uint32_t sbase, int buf, const BlkA& b, int tid) {
    const uint32_t aOff = OFF_A + (uint32_t)buf * TILEB;
    const uint32_t bOff = OFF_B + (uint32_t)buf * TILEB;
    #pragma unroll
    for (int i = 0; i < 5; i++) {
        int idx = tid + i * NTHREADS;        // 0..1279
        int r = idx / 10, ch = idx - r * 10;
        cp16(sbase + aOff + (uint32_t)r * ASTB + ch * 16,
             (const char*)(g_xq + (size_t)(b.m0 + r) * KWORDS) + b.koff + ch * 16);
        cp16(sbase + bOff + (uint32_t)r * ASTB + ch * 16,
             (const char*)(g_cq + (size_t)(b.n0 + r) * KWORDS) + b.koff + ch * 16);
    }
    CP_COMMIT();
}

// ---------------------------------------------------------------------------
// Persistent main kernel: fp8 mma, 3-stage cp.async pipeline continuous
// across work-unit boundaries; register epilogue with exact underflow skip
// ---------------------------------------------------------------------------
__global__ __launch_bounds__(NTHREADS, 1)
void rbf_mma_kernel(const float* __restrict__ W) {
    extern __shared__ char sm[];
    const uint32_t sbase = smem_u32(sm);

    const int tid  = threadIdx.x;
    const int wid  = tid >> 5;
    const int lane = tid & 31;
    const int wm   = wid & 3;
    const int wn   = wid >> 2;
    const int lm   = lane >> 2;
    const int ln   = (lane & 3) * 2;
    const int cta  = blockIdx.x;
    const int strd = gridDim.x;

    float* c2S   = (float*)(sm + OFF_C2);
    float* is2S  = (float*)(sm + OFF_IS2);
    float* WcolS = (float*)(sm + OFF_WCOL);
    float* redS  = (float*)(sm + OFF_RED);

    const int n_units = (NUNITS - cta + strd - 1) / strd;
    const int NB = n_units * BPU;
    if (n_units <= 0) return;

    issue_tile(sbase, 0, blk_addr(0, cta, strd), tid);
    if (NB > 1) issue_tile(sbase, 1, blk_addr(1, cta, strd), tid);

    float oacc[4][OUT_DIM];
    #pragma unroll
    for (int i = 0; i < 4; i++)
        #pragma unroll
        for (int o = 0; o < OUT_DIM; o++) oacc[i][o] = 0.f;

    float acc[2][8][4];
    float x2a0 = 0.f, x2b0 = 0.f, x2a1 = 0.f, x2b1 = 0.f;

    for (int gb = 0; gb < NB; gb++) {
        const BlkA b = blk_addr(gb, cta, strd);
        const int buf = gb % NSTAGE;

        if (b.kb == 0) {
            if (b.cl == 0) {
                const int ra0 = b.m0 + wm * 32 + lm;
                x2a0 = g_x2[ra0];      x2b0 = g_x2[ra0 + 8];
                x2a1 = g_x2[ra0 + 16]; x2b1 = g_x2[ra0 + 24];
            }
            if (tid < TN) {
                c2S[tid]  = g_c2[b.n0 + tid];
                is2S[tid] = g_is2[b.n0 + tid];
            }
            #pragma unroll
            for (int i = 0; i < 5; i++) {
                int idx = tid + i * NTHREADS;      // TN*OUT = 1280
                int cc = idx / OUT_DIM, o = idx - cc * OUT_DIM;
                WcolS[cc * WST + o] = W[(size_t)o * C_DIM + b.n0 + cc];
            }
            #pragma unroll
            for (int i = 0; i < 2; i++)
                #pragma unroll
                for (int j = 0; j < 8; j++)
                    #pragma unroll
                    for (int e = 0; e < 4; e++) acc[i][j][e] = 0.f;
        }

        if (gb + 1 < NB) CP_WAIT1(); else CP_WAIT0();
        __syncthreads();   // tile + metadata visible CTA-wide

        if (gb + 2 < NB)
            issue_tile(sbase, (gb + 2) % NSTAGE, blk_addr(gb + 2, cta, strd), tid);

        const uint32_t aBase = sbase + OFF_A + (uint32_t)buf * TILEB;
        const uint32_t bBase = sbase + OFF_B + (uint32_t)buf * TILEB;
        const uint32_t lrow  = (uint32_t)(lane & 15);
        const uint32_t lcol  = (uint32_t)(lane >> 4) * 16u;

        #pragma unroll
        for (int ks = 0; ks < NK32; ks++) {
            uint32_t af[2][4];
            #pragma unroll
            for (int mi = 0; mi < 2; mi++)
                ldm_x4(af[mi], aBase + (uint32_t)(wm * 32 + mi * 16 + lrow) * ASTB
                                     + (uint32_t)ks * 32u + lcol);
            uint32_t bf[8][2];
            #pragma unroll
            for (int njj = 0; njj < 4; njj++) {
                uint32_t r4[4];
                ldm_x4(r4, bBase + (uint32_t)(wn * 64 + njj * 16 + lrow) * ASTB
                                 + (uint32_t)ks * 32u + lcol);
                bf[njj * 2 + 0][0] = r4[0];
                bf[njj * 2 + 1][0] = r4[1];
                bf[njj * 2 + 0][1] = r4[2];
                bf[njj * 2 + 1][1] = r4[3];
            }
            #pragma unroll
            for (int mi = 0; mi < 2; mi++)
                #pragma unroll
                for (int nf = 0; nf < 8; nf++)
                    mma16832_fp8(acc[mi][nf], af[mi], bf[nf]);
        }

        if (b.kb == NKBLK - 1) {
            // ---- chunk epilogue: t = d2*is2; exp(-t)==0 exactly for t>104 ----
            #pragma unroll
            for (int nf = 0; nf < 8; nf++) {
                const int c0 = wn * 64 + nf * 8 + ln;
                const int c1 = c0 + 1;
                const float cc0 = c2S[c0],  cc1 = c2S[c1];
                const float ii0 = is2S[c0], ii1 = is2S[c1];
                #pragma unroll
                for (int mi = 0; mi < 2; mi++) {
                    const float xa = mi ? x2a1 : x2a0;
                    const float xb = mi ? x2b1 : x2b0;
                    const float t00 = fmaxf(xa + cc0 - 2.f * acc[mi][nf][0], 0.f) * ii0;
                    const float t01 = fmaxf(xa + cc1 - 2.f * acc[mi][nf][1], 0.f) * ii1;
                    const float t10 = fmaxf(xb + cc0 - 2.f * acc[mi][nf][2], 0.f) * ii0;
                    const float t11 = fmaxf(xb + cc1 - 2.f * acc[mi][nf][3], 0.f) * ii1;
                    if (t00 < 104.f || t01 < 104.f || t10 < 104.f || t11 < 104.f) {
                        const float p00 = __expf(-t00);
                        const float p01 = __expf(-t01);
                        const float p10 = __expf(-t10);
                        const float p11 = __expf(-t11);
                        #pragma unroll
                        for (int o = 0; o < OUT_DIM; o++) {
                            const float w0 = WcolS[c0 * WST + o];
                            const float w1 = WcolS[c1 * WST + o];
                            oacc[mi * 2 + 0][o] = fmaf(p00, w0, fmaf(p01, w1, oacc[mi * 2 + 0][o]));
                            oacc[mi * 2 + 1][o] = fmaf(p10, w0, fmaf(p11, w1, oacc[mi * 2 + 1][o]));
                        }
                    }
                }
            }
            __syncthreads();   // meta consumed; next chunk may overwrite

            if (b.cl == CHPS - 1) {
                // ---- unit-end: cross-lane + cross-warp reduce, write partial ----
                #pragma unroll
                for (int i = 0; i < 4; i++)
                    #pragma unroll
                    for (int o = 0; o < OUT_DIM; o++) {
                        float v = oacc[i][o];
                        v += __shfl_xor_sync(0xffffffffu, v, 1);
                        v += __shfl_xor_sync(0xffffffffu, v, 2);
                        oacc[i][o] = v;
                    }
                if (wn == 0 && (lane & 3) == 0) {
                    #pragma unroll
                    for (int i = 0; i < 4; i++) {
                        const int r = wm * 32 + (i >> 1) * 16 + (i & 1) * 8 + lm;
                        #pragma unroll
                        for (int o = 0; o < OUT_DIM; o++) redS[r * WST + o] = oacc[i][o];
                    }
                }
                __syncthreads();
                if (wn == 1 && (lane & 3) == 0) {
                    #pragma unroll
                    for (int i = 0; i < 4; i++) {
                        const int r = wm * 32 + (i >> 1) * 16 + (i & 1) * 8 + lm;
                        #pragma unroll
                        for (int o = 0; o < OUT_DIM; o++) redS[r * WST + o] += oacc[i][o];
                    }
                }
                __syncthreads();

                const int slice = b.unit & (NSLICE - 1);
                float* pbase = g_part + (size_t)slice * B_ROWS * OUT_DIM
                             + (size_t)b.m0 * OUT_DIM;
                for (int e = tid; e < TM * OUT_DIM; e += NTHREADS) {
                    const int r = e / OUT_DIM;
                    const int o = e - r * OUT_DIM;
                    pbase[(size_t)r * OUT_DIM + o] = redS[r * WST + o];
                }
                #pragma unroll
                for (int i = 0; i < 4; i++)
                    #pragma unroll
                    for (int o = 0; o < OUT_DIM; o++) oacc[i][o] = 0.f;
                __syncthreads();   // redS consumed before next unit reuses it
            }
        }
    }
}

// ---------------------------------------------------------------------------
// Reduce: out = sum of 8 slice partials + bias  (float4 vectorized)
// ---------------------------------------------------------------------------
__global__ void reduce_kernel(const float* __restrict__ bias, float* __restrict__ out) {
    const int t = blockIdx.x * blockDim.x + threadIdx.x;       // float4 index
    const int NQ = (B_ROWS * OUT_DIM) / 4;                     // 40960
    if (t >= NQ) return;
    const int i0 = t * 4;
    float4 s;
    s.x = __ldg(&bias[(i0 + 0) % OUT_DIM]);
    s.y = __ldg(&bias[(i0 + 1) % OUT_DIM]);
    s.z = __ldg(&bias[(i0 + 2) % OUT_DIM]);
    s.w = __ldg(&bias[(i0 + 3) % OUT_DIM]);
    #pragma unroll
    for (int sl = 0; sl < NSLICE; sl++) {
        const float4 p = *(const float4*)&g_part[(size_t)sl * B_ROWS * OUT_DIM + i0];
        s.x += p.x; s.y += p.y; s.z += p.z; s.w += p.w;
    }
    ((float4*)out)[t] = s;
}

// ---------------------------------------------------------------------------
// Launch
// ---------------------------------------------------------------------------
extern "C" void kernel_launch(void* const* d_in, const int* in_sizes, int n_in,
                              void* d_out, int out_size) {
    const float* x       = (const float*)d_in[0];
    const float* centres = (const float*)d_in[1];
    const float* ls      = (const float*)d_in[2];
    const float* W       = (const float*)d_in[3];
    const float* bias    = (const float*)d_in[4];
    float* out           = (float*)d_out;

    int nsm = 148;
    cudaDeviceGetAttribute(&nsm, cudaDevAttrMultiProcessorCount, 0);

    const int nwarps = B_ROWS + C_DIM;              // 18432
    prep_kernel<<<nwarps / 8, 256>>>(x, centres, ls);

    cudaFuncSetAttribute(rbf_mma_kernel,
                         cudaFuncAttributeMaxDynamicSharedMemorySize, SMEM_TOTAL);
    rbf_mma_kernel<<<nsm, NTHREADS, SMEM_TOTAL>>>(W);

    reduce_kernel<<<((B_ROWS * OUT_DIM) / 4 + 255) / 256, 256>>>(bias, out);
}

// round 15
// speedup vs baseline: 1.1109x; 1.0206x over previous
#include <cuda_runtime.h>
#include <cuda_fp8.h>
#include <cstdint>

// ---------------------------------------------------------------------------
// Problem constants
// ---------------------------------------------------------------------------
#define B_ROWS  16384
#define D_DIM   784
#define C_DIM   2048
#define OUT_DIM 10

#define KPAD   800               // 784 padded to 25*32 (fp8 bytes)
#define KWORDS 200               // KPAD/4
#define KB     160               // K bytes per pipeline block
#define NKBLK  5                 // blocks per chunk (5*160 = 800)
#define NK32   5                 // k32 steps per block
#define TM     128               // x rows per unit
#define TN     128               // centres per chunk
#define NSLICE 8                 // C split across units
#define CHPS   2                 // chunks per unit (256 centres)
#define BPU    (CHPS * NKBLK)    // 10 blocks per unit
#define NUNITS ((B_ROWS / TM) * NSLICE)   // 1024 work units
#define NTHREADS 256

// smem tile stride: 160 data + 16 pad bytes (ldmatrix phases r*11 mod 8 distinct)
#define ASTB  176
#define TILEB 22528u             // 128 * 176
#define NSTAGE 3
#define WST   12                 // floats per red row (10 + 2 pad)

// smem byte offsets (Wcol staging removed: W read via L2 in the rare branch)
#define OFF_A    0u                       // 3 x 22528 = 67584
#define OFF_B    67584u                   // 3 x 22528 = 67584
#define OFF_C2   135168u                  // 128 x 4
#define OFF_IS2  135680u                  // 128 x 4
#define OFF_RED  136192u                  // 128 x 12 x 4 = 6144
#define SMEM_TOTAL 142336u

// ---------------------------------------------------------------------------
// Device-global scratch (no allocations allowed)
// ---------------------------------------------------------------------------
__device__ __align__(16) uint32_t g_xq[(size_t)B_ROWS * KWORDS];   // 13.1 MB fp8
__device__ __align__(16) uint32_t g_cq[(size_t)C_DIM * KWORDS];    // 1.6 MB fp8
__device__ float g_x2[B_ROWS];
__device__ float g_c2[C_DIM];
__device__ float g_is2[C_DIM];
__device__ __align__(16) float g_part[(size_t)NSLICE * B_ROWS * OUT_DIM]; // 5.2 MB

// ---------------------------------------------------------------------------
// PTX helpers (base-ISA sm_80/89 era; valid for compute_103 virtual arch)
// ---------------------------------------------------------------------------
__device__ __forceinline__ uint32_t smem_u32(const void* p) {
    uint32_t a;
    asm("{ .reg .u64 t; cvta.to.shared.u64 t, %1; cvt.u32.u64 %0, t; }" : "=r"(a) : "l"(p));
    return a;
}

__device__ __forceinline__ void cp16(uint32_t dst, const void* src) {
    asm volatile("cp.async.cg.shared.global [%0], [%1], 16;" :: "r"(dst), "l"(src));
}
#define CP_COMMIT() asm volatile("cp.async.commit_group;" ::: "memory")
#define CP_WAIT0()  asm volatile("cp.async.wait_group 0;"  ::: "memory")
#define CP_WAIT1()  asm volatile("cp.async.wait_group 1;"  ::: "memory")

__device__ __forceinline__ void ldm_x4(uint32_t* r, uint32_t addr) {
    asm volatile("ldmatrix.sync.aligned.m8n8.x4.shared.b16 {%0,%1,%2,%3}, [%4];"
                 : "=r"(r[0]), "=r"(r[1]), "=r"(r[2]), "=r"(r[3]) : "r"(addr));
}

// fp8 e4m3 MMA: m16n8k32, f32 accum (sm_89+ base ISA; full SIMT rate on sm_103a)
__device__ __forceinline__ void mma16832_fp8(float* c, const uint32_t* a, const uint32_t* b) {
    asm volatile(
        "mma.sync.aligned.m16n8k32.row.col.f32.e4m3.e4m3.f32 "
        "{%0,%1,%2,%3}, {%4,%5,%6,%7}, {%8,%9}, {%0,%1,%2,%3};"
        : "+f"(c[0]), "+f"(c[1]), "+f"(c[2]), "+f"(c[3])
        : "r"(a[0]), "r"(a[1]), "r"(a[2]), "r"(a[3]), "r"(b[0]), "r"(b[1]));
}

__device__ __forceinline__ uint32_t quad_to_fp8(float4 v) {
    __nv_fp8x2_storage_t lo = __nv_cvt_float2_to_fp8x2(make_float2(v.x, v.y),
                                                       __NV_SATFINITE, __NV_E4M3);
    __nv_fp8x2_storage_t hi = __nv_cvt_float2_to_fp8x2(make_float2(v.z, v.w),
                                                       __NV_SATFINITE, __NV_E4M3);
    return (uint32_t)lo | ((uint32_t)hi << 16);
}

// ---------------------------------------------------------------------------
// Fused prep: fp8 conversion (padded) + row squared norms. One warp per row;
// handles both x (rows < B_ROWS) and centres.
// ---------------------------------------------------------------------------
__global__ __launch_bounds__(256)
void prep_kernel(const float* __restrict__ x,
                 const float* __restrict__ c,
                 const float* __restrict__ ls) {
    const int gw   = (blockIdx.x * blockDim.x + threadIdx.x) >> 5;
    const int lane = threadIdx.x & 31;
    const bool isX = gw < B_ROWS;
    const int row  = isX ? gw : gw - B_ROWS;
    if (!isX && row >= C_DIM) return;

    const float4* src = (const float4*)((isX ? x : c) + (size_t)row * D_DIM);
    uint32_t* dst = (isX ? g_xq : g_cq) + (size_t)row * KWORDS;

    float4 v[7];
    #pragma unroll
    for (int i = 0; i < 6; i++) v[i] = src[lane + i * 32];
    const int wt = 192 + lane;
    v[6] = (lane < 4) ? src[wt] : make_float4(0.f, 0.f, 0.f, 0.f);

    float s = 0.f;
    #pragma unroll
    for (int i = 0; i < 7; i++)
        s = fmaf(v[i].x, v[i].x, fmaf(v[i].y, v[i].y,
            fmaf(v[i].z, v[i].z, fmaf(v[i].w, v[i].w, s))));

    #pragma unroll
    for (int i = 0; i < 6; i++) dst[lane + i * 32] = quad_to_fp8(v[i]);
    if (lane < 8) dst[wt] = quad_to_fp8(v[6]);   // words 196..199 write zeros

    #pragma unroll
    for (int m = 16; m; m >>= 1) s += __shfl_xor_sync(0xffffffffu, s, m);
    if (lane == 0) {
        if (isX) g_x2[row] = s;
        else     { g_c2[row] = s; g_is2[row] = __expf(-2.f * ls[row]); }
    }
}

// ---------------------------------------------------------------------------
// Per-block address helper for the flattened persistent pipeline
// ---------------------------------------------------------------------------
struct BlkA { int m0, n0, koff, kb, cl, unit; };
__device__ __forceinline__ BlkA blk_addr(int gb, int cta, int stride) {
    BlkA b;
    const int ui  = gb / BPU;
    const int rem = gb - ui * BPU;
    b.cl   = rem / NKBLK;
    b.kb   = rem - b.cl * NKBLK;
    b.unit = cta + ui * stride;
    b.m0   = (b.unit >> 3) * TM;
    b.n0   = ((b.unit & (NSLICE - 1)) * CHPS + b.cl) * TN;
    b.koff = b.kb * KB;
    return b;
}

__device__ __forceinline__ void issue_tile(uint32_t sbase, int buf, const BlkA& b, int tid) {
    const uint32_t aOff = OFF_A + (uint32_t)buf * TILEB;
    const uint32_t bOff = OFF_B + (uint32_t)buf * TILEB;
    #pragma unroll
    for (int i = 0; i < 5; i++) {
        int idx = tid + i * NTHREADS;        // 0..1279
        int r = idx / 10, ch = idx - r * 10;
        cp16(sbase + aOff + (uint32_t)r * ASTB + ch * 16,
             (const char*)(g_xq + (size_t)(b.m0 + r) * KWORDS) + b.koff + ch * 16);
        cp16(sbase + bOff + (uint32_t)r * ASTB + ch * 16,
             (const char*)(g_cq + (size_t)(b.n0 + r) * KWORDS) + b.koff + ch * 16);
    }
    CP_COMMIT();
}

// ---------------------------------------------------------------------------
// Persistent main kernel: fp8 mma, 3-stage cp.async pipeline continuous
// across work-unit boundaries; register epilogue with exact underflow skip.
// W is NOT staged in smem: it is consumed only inside the guarded (rare)
// branch, where direct L2 loads are cheap; the common path gets lighter.
// ---------------------------------------------------------------------------
__global__ __launch_bounds__(NTHREADS, 1)
void rbf_mma_kernel(const float* __restrict__ W) {
    extern __shared__ char sm[];
    const uint32_t sbase = smem_u32(sm);

    const int tid  = threadIdx.x;
    const int wid  = tid >> 5;
    const int lane = tid & 31;
    const int wm   = wid & 3;
    const int wn   = wid >> 2;
    const int lm   = lane >> 2;
    const int ln   = (lane & 3) * 2;
    const int cta  = blockIdx.x;
    const int strd = gridDim.x;

    float* c2S   = (float*)(sm + OFF_C2);
    float* is2S  = (float*)(sm + OFF_IS2);
    float* redS  = (float*)(sm + OFF_RED);

    const int n_units = (NUNITS - cta + strd - 1) / strd;
    const int NB = n_units * BPU;
    if (n_units <= 0) return;

    issue_tile(sbase, 0, blk_addr(0, cta, strd), tid);
    if (NB > 1) issue_tile(sbase, 1, blk_addr(1, cta, strd), tid);

    float oacc[4][OUT_DIM];
    #pragma unroll
    for (int i = 0; i < 4; i++)
        #pragma unroll
        for (int o = 0; o < OUT_DIM; o++) oacc[i][o] = 0.f;

    float acc[2][8][4];
    float x2a0 = 0.f, x2b0 = 0.f, x2a1 = 0.f, x2b1 = 0.f;

    for (int gb = 0; gb < NB; gb++) {
        const BlkA b = blk_addr(gb, cta, strd);
        const int buf = gb % NSTAGE;

        if (b.kb == 0) {
            if (b.cl == 0) {
                const int ra0 = b.m0 + wm * 32 + lm;
                x2a0 = g_x2[ra0];      x2b0 = g_x2[ra0 + 8];
                x2a1 = g_x2[ra0 + 16]; x2b1 = g_x2[ra0 + 24];
            }
            if (tid < TN) {
                c2S[tid]  = g_c2[b.n0 + tid];
                is2S[tid] = g_is2[b.n0 + tid];
            }
            #pragma unroll
            for (int i = 0; i < 2; i++)
                #pragma unroll
                for (int j = 0; j < 8; j++)
                    #pragma unroll
                    for (int e = 0; e < 4; e++) acc[i][j][e] = 0.f;
        }

        if (gb + 1 < NB) CP_WAIT1(); else CP_WAIT0();
        __syncthreads();   // tile + metadata visible CTA-wide

        if (gb + 2 < NB)
            issue_tile(sbase, (gb + 2) % NSTAGE, blk_addr(gb + 2, cta, strd), tid);

        const uint32_t aBase = sbase + OFF_A + (uint32_t)buf * TILEB;
        const uint32_t bBase = sbase + OFF_B + (uint32_t)buf * TILEB;
        const uint32_t lrow  = (uint32_t)(lane & 15);
        const uint32_t lcol  = (uint32_t)(lane >> 4) * 16u;

        #pragma unroll
        for (int ks = 0; ks < NK32; ks++) {
            uint32_t af[2][4];
            #pragma unroll
            for (int mi = 0; mi < 2; mi++)
                ldm_x4(af[mi], aBase + (uint32_t)(wm * 32 + mi * 16 + lrow) * ASTB
                                     + (uint32_t)ks * 32u + lcol);
            uint32_t bf[8][2];
            #pragma unroll
            for (int njj = 0; njj < 4; njj++) {
                uint32_t r4[4];
                ldm_x4(r4, bBase + (uint32_t)(wn * 64 + njj * 16 + lrow) * ASTB
                                 + (uint32_t)ks * 32u + lcol);
                bf[njj * 2 + 0][0] = r4[0];
                bf[njj * 2 + 1][0] = r4[1];
                bf[njj * 2 + 0][1] = r4[2];
                bf[njj * 2 + 1][1] = r4[3];
            }
            #pragma unroll
            for (int mi = 0; mi < 2; mi++)
                #pragma unroll
                for (int nf = 0; nf < 8; nf++)
                    mma16832_fp8(acc[mi][nf], af[mi], bf[nf]);
        }

        if (b.kb == NKBLK - 1) {
            // ---- chunk epilogue: t = d2*is2; exp(-t)==0 exactly for t>104.
            //      W loaded from gmem (L2) only inside the rare branch. ----
            #pragma unroll
            for (int nf = 0; nf < 8; nf++) {
                const int c0 = wn * 64 + nf * 8 + ln;
                const int c1 = c0 + 1;
                const float cc0 = c2S[c0],  cc1 = c2S[c1];
                const float ii0 = is2S[c0], ii1 = is2S[c1];
                #pragma unroll
                for (int mi = 0; mi < 2; mi++) {
                    const float xa = mi ? x2a1 : x2a0;
                    const float xb = mi ? x2b1 : x2b0;
                    const float t00 = fmaxf(xa + cc0 - 2.f * acc[mi][nf][0], 0.f) * ii0;
                    const float t01 = fmaxf(xa + cc1 - 2.f * acc[mi][nf][1], 0.f) * ii1;
                    const float t10 = fmaxf(xb + cc0 - 2.f * acc[mi][nf][2], 0.f) * ii0;
                    const float t11 = fmaxf(xb + cc1 - 2.f * acc[mi][nf][3], 0.f) * ii1;
                    if (t00 < 104.f || t01 < 104.f || t10 < 104.f || t11 < 104.f) {
                        const float p00 = __expf(-t00);
                        const float p01 = __expf(-t01);
                        const float p10 = __expf(-t10);
                        const float p11 = __expf(-t11);
                        const float* w0p = W + (size_t)(b.n0 + c0);
                        const float* w1p = W + (size_t)(b.n0 + c1);
                        #pragma unroll
                        for (int o = 0; o < OUT_DIM; o++) {
                            const float w0 = __ldg(w0p + (size_t)o * C_DIM);
                            const float w1 = __ldg(w1p + (size_t)o * C_DIM);
                            oacc[mi * 2 + 0][o] = fmaf(p00, w0, fmaf(p01, w1, oacc[mi * 2 + 0][o]));
                            oacc[mi * 2 + 1][o] = fmaf(p10, w0, fmaf(p11, w1, oacc[mi * 2 + 1][o]));
                        }
                    }
                }
            }
            __syncthreads();   // c2/is2 consumed; next chunk may overwrite

            if (b.cl == CHPS - 1) {
                // ---- unit-end: cross-lane + cross-warp reduce, write partial ----
                #pragma unroll
                for (int i = 0; i < 4; i++)
                    #pragma unroll
                    for (int o = 0; o < OUT_DIM; o++) {
                        float v = oacc[i][o];
                        v += __shfl_xor_sync(0xffffffffu, v, 1);
                        v += __shfl_xor_sync(0xffffffffu, v, 2);
                        oacc[i][o] = v;
                    }
                if (wn == 0 && (lane & 3) == 0) {
                    #pragma unroll
                    for (int i = 0; i < 4; i++) {
                        const int r = wm * 32 + (i >> 1) * 16 + (i & 1) * 8 + lm;
                        #pragma unroll
                        for (int o = 0; o < OUT_DIM; o++) redS[r * WST + o] = oacc[i][o];
                    }
                }
                __syncthreads();
                if (wn == 1 && (lane & 3) == 0) {
                    #pragma unroll
                    for (int i = 0; i < 4; i++) {
                        const int r = wm * 32 + (i >> 1) * 16 + (i & 1) * 8 + lm;
                        #pragma unroll
                        for (int o = 0; o < OUT_DIM; o++) redS[r * WST + o] += oacc[i][o];
                    }
                }
                __syncthreads();

                const int slice = b.unit & (NSLICE - 1);
                float* pbase = g_part + (size_t)slice * B_ROWS * OUT_DIM
                             + (size_t)b.m0 * OUT_DIM;
                for (int e = tid; e < TM * OUT_DIM; e += NTHREADS) {
                    const int r = e / OUT_DIM;
                    const int o = e - r * OUT_DIM;
                    pbase[(size_t)r * OUT_DIM + o] = redS[r * WST + o];
                }
                #pragma unroll
                for (int i = 0; i < 4; i++)
                    #pragma unroll
                    for (int o = 0; o < OUT_DIM; o++) oacc[i][o] = 0.f;
                __syncthreads();   // redS consumed before next unit reuses it
            }
        }
    }
}

// ---------------------------------------------------------------------------
// Reduce: out = sum of 8 slice partials + bias  (float4 vectorized)
// ---------------------------------------------------------------------------
__global__ void reduce_kernel(const float* __restrict__ bias, float* __restrict__ out) {
    const int t = blockIdx.x * blockDim.x + threadIdx.x;       // float4 index
    const int NQ = (B_ROWS * OUT_DIM) / 4;                     // 40960
    if (t >= NQ) return;
    const int i0 = t * 4;
    float4 s;
    s.x = __ldg(&bias[(i0 + 0) % OUT_DIM]);
    s.y = __ldg(&bias[(i0 + 1) % OUT_DIM]);
    s.z = __ldg(&bias[(i0 + 2) % OUT_DIM]);
    s.w = __ldg(&bias[(i0 + 3) % OUT_DIM]);
    #pragma unroll
    for (int sl = 0; sl < NSLICE; sl++) {
        const float4 p = *(const float4*)&g_part[(size_t)sl * B_ROWS * OUT_DIM + i0];
        s.x += p.x; s.y += p.y; s.z += p.z; s.w += p.w;
    }
    ((float4*)out)[t] = s;
}

// ---------------------------------------------------------------------------
// Launch
// ---------------------------------------------------------------------------
extern "C" void kernel_launch(void* const* d_in, const int* in_sizes, int n_in,
                              void* d_out, int out_size) {
    const float* x       = (const float*)d_in[0];
    const float* centres = (const float*)d_in[1];
    const float* ls      = (const float*)d_in[2];
    const float* W       = (const float*)d_in[3];
    const float* bias    = (const float*)d_in[4];
    float* out           = (float*)d_out;

    int nsm = 148;
    cudaDeviceGetAttribute(&nsm, cudaDevAttrMultiProcessorCount, 0);

    const int nwarps = B_ROWS + C_DIM;              // 18432
    prep_kernel<<<nwarps / 8, 256>>>(x, centres, ls);

    cudaFuncSetAttribute(rbf_mma_kernel,
                         cudaFuncAttributeMaxDynamicSharedMemorySize, SMEM_TOTAL);
    rbf_mma_kernel<<<nsm, NTHREADS, SMEM_TOTAL>>>(W);

    reduce_kernel<<<((B_ROWS * OUT_DIM) / 4 + 255) / 256, 256>>>(bias, out);
}